// round 7
// baseline (speedup 1.0000x reference)
#include <cuda_runtime.h>
#include <cstdint>

#define NP 500000
#define NB 20000
#define NC 5000
#define NS 2000
#define NTOT 527000
#define NE 500000
#define EDIR (3 * NE * 2)
#define H 64
#define FIN 384

#define SCAN_SPAN 2048
#define NBLK_SCAN ((NTOT + SCAN_SPAN - 1) / SCAN_SPAN)

// ---------------- scratch ----------------------------------------------------
__device__ float g_x[(size_t)NTOT * H];
__device__ float g_h[(size_t)NTOT * H];
__device__ float g_agg[(size_t)NTOT * H];
__device__ int   g_deg[NTOT];
__device__ int   g_rowstart[NTOT];
__device__ int   g_cursor[NTOT];
__device__ int   g_scaninc[NTOT];
__device__ int   g_blocksum[512];
__device__ int   g_adj[EDIR];

// ---------------- tf32 helpers ----------------------------------------------
__device__ __forceinline__ uint32_t f2tf(float x) {
    uint32_t r;
    asm("cvt.rna.tf32.f32 %0, %1;" : "=r"(r) : "f"(x));
    return r;
}
__device__ __forceinline__ void mma_tf32(float* d, uint32_t a0, uint32_t a1,
                                         uint32_t a2, uint32_t a3,
                                         uint32_t b0, uint32_t b1) {
    asm volatile(
        "mma.sync.aligned.m16n8k8.row.col.f32.tf32.tf32.f32 "
        "{%0,%1,%2,%3},{%4,%5,%6,%7},{%8,%9},{%0,%1,%2,%3};"
        : "+f"(d[0]), "+f"(d[1]), "+f"(d[2]), "+f"(d[3])
        : "r"(a0), "r"(a1), "r"(a2), "r"(a3), "r"(b0), "r"(b1));
}

// ---------------- CSR build ---------------------------------------------------
__global__ void __launch_bounds__(256) zero_deg() {
    int i = blockIdx.x * 256 + threadIdx.x;
    if (i < NTOT) g_deg[i] = 0;
}

__global__ void __launch_bounds__(256) hist_edges(
    const int* __restrict__ pb_src, const int* __restrict__ pb_dst,
    const int* __restrict__ pc_src, const int* __restrict__ pc_dst,
    const int* __restrict__ ps_src, const int* __restrict__ ps_dst) {
    int e = blockIdx.x * 256 + threadIdx.x;
    if (e >= 3 * NE) return;
    int t = e / NE, i = e - t * NE;
    const int* sp; const int* dp; int off;
    if (t == 0)      { sp = pb_src; dp = pb_dst; off = NP; }
    else if (t == 1) { sp = pc_src; dp = pc_dst; off = NP + NB; }
    else             { sp = ps_src; dp = ps_dst; off = NP + NB + NC; }
    int p = __ldg(sp + i);
    int o = __ldg(dp + i) + off;
    atomicAdd(&g_deg[p], 1);
    atomicAdd(&g_deg[o], 1);
}

__global__ void __launch_bounds__(256) scanA() {
    __shared__ int wsum[8];
    __shared__ int wpre[8];
    int tid = threadIdx.x, lane = tid & 31, wid = tid >> 5;
    int base = blockIdx.x * SCAN_SPAN + tid * 8;
    int v[8], run = 0;
#pragma unroll
    for (int t = 0; t < 8; t++) {
        int idx = base + t;
        int d = (idx < NTOT) ? g_deg[idx] : 0;
        run += d;
        v[t] = run;
    }
    int tot = run;
#pragma unroll
    for (int off = 1; off < 32; off <<= 1) {
        int n = __shfl_up_sync(0xffffffffu, tot, off);
        if (lane >= off) tot += n;
    }
    int wexcl = tot - run;
    if (lane == 31) wsum[wid] = tot;
    __syncthreads();
    if (tid < 8) {
        int s = wsum[tid];
        int r = s;
#pragma unroll
        for (int off = 1; off < 8; off <<= 1) {
            int n = __shfl_up_sync(0xffu, r, off);
            if (tid >= off) r += n;
        }
        wpre[tid] = r - s;
        if (tid == 7) g_blocksum[blockIdx.x] = r;
    }
    __syncthreads();
    int bexcl = wexcl + wpre[wid];
#pragma unroll
    for (int t = 0; t < 8; t++) {
        int idx = base + t;
        if (idx < NTOT) g_scaninc[idx] = v[t] + bexcl;
    }
}

__global__ void __launch_bounds__(512) scanB() {
    __shared__ int s[NBLK_SCAN];
    int tid = threadIdx.x;
    if (tid < NBLK_SCAN) s[tid] = g_blocksum[tid];
    __syncthreads();
    if (tid == 0) {
        int run = 0;
        for (int i = 0; i < NBLK_SCAN; i++) { int t = s[i]; s[i] = run; run += t; }
    }
    __syncthreads();
    if (tid < NBLK_SCAN) g_blocksum[tid] = s[tid];
}

__global__ void __launch_bounds__(256) scanC() {
    int i = blockIdx.x * 256 + threadIdx.x;
    if (i >= NTOT) return;
    int start = g_scaninc[i] + g_blocksum[i >> 11] - g_deg[i];
    g_rowstart[i] = start;
    g_cursor[i] = start;
}

__global__ void __launch_bounds__(256) fill_csr(
    const int* __restrict__ pb_src, const int* __restrict__ pb_dst,
    const int* __restrict__ pc_src, const int* __restrict__ pc_dst,
    const int* __restrict__ ps_src, const int* __restrict__ ps_dst) {
    int e = blockIdx.x * 256 + threadIdx.x;
    if (e >= 3 * NE) return;
    int t = e / NE, i = e - t * NE;
    const int* sp; const int* dp; int off;
    if (t == 0)      { sp = pb_src; dp = pb_dst; off = NP; }
    else if (t == 1) { sp = pc_src; dp = pc_dst; off = NP + NB; }
    else             { sp = ps_src; dp = ps_dst; off = NP + NB + NC; }
    int p = __ldg(sp + i);
    int o = __ldg(dp + i) + off;
    int pos = atomicAdd(&g_cursor[o], 1);
    g_adj[pos] = p;
    int pos2 = atomicAdd(&g_cursor[p], 1);
    g_adj[pos2] = o;
}

// ---------------- feature assembly --------------------------------------------
__global__ void __launch_bounds__(256) copy_emb(const float* __restrict__ eb,
                                                const float* __restrict__ ec,
                                                const float* __restrict__ es) {
    int i = blockIdx.x * 256 + threadIdx.x;
    const int tot = (NB + NC + NS) * H / 4;
    if (i >= tot) return;
    const int nb4 = NB * H / 4, nc4 = NC * H / 4;
    float4 v;
    if (i < nb4) v = reinterpret_cast<const float4*>(eb)[i];
    else if (i < nb4 + nc4) v = reinterpret_cast<const float4*>(ec)[i - nb4];
    else v = reinterpret_cast<const float4*>(es)[i - nb4 - nc4];
    reinterpret_cast<float4*>(g_x)[(size_t)NP * H / 4 + i] = v;
}

// ---------------- proj: relu(x_product @ W_proj^T + b) via tf32 HMMA ----------
__global__ void __launch_bounds__(256) proj_tc(const float* __restrict__ A,
                                               const float* __restrict__ W,
                                               const float* __restrict__ bias) {
    __shared__ uint32_t As[128][20];
    __shared__ uint32_t Ws[64][20];
    const int tid = threadIdx.x;
    const int m0 = blockIdx.x * 128;
    const int warp = tid >> 5, lane = tid & 31;
    const int g = lane >> 2, t = lane & 3;

    float acc[8][4];
#pragma unroll
    for (int j = 0; j < 8; j++)
#pragma unroll
        for (int c = 0; c < 4; c++) acc[j][c] = 0.f;

    for (int kb = 0; kb < FIN; kb += 16) {
#pragma unroll
        for (int q = 0; q < 2; q++) {
            int idx = tid + 256 * q;
            int row = idx >> 2, c4 = idx & 3;
            int rg = m0 + row; if (rg > NP - 1) rg = NP - 1;
            float4 v = *reinterpret_cast<const float4*>(A + (size_t)rg * FIN + kb + c4 * 4);
            uint4 u = make_uint4(f2tf(v.x), f2tf(v.y), f2tf(v.z), f2tf(v.w));
            *reinterpret_cast<uint4*>(&As[row][c4 * 4]) = u;
        }
        {
            int n = tid >> 2, c4 = tid & 3;
            float4 v = *reinterpret_cast<const float4*>(W + (size_t)n * FIN + kb + c4 * 4);
            uint4 u = make_uint4(f2tf(v.x), f2tf(v.y), f2tf(v.z), f2tf(v.w));
            *reinterpret_cast<uint4*>(&Ws[n][c4 * 4]) = u;
        }
        __syncthreads();
        const int r0 = warp * 16;
#pragma unroll
        for (int ks = 0; ks < 2; ks++) {
            int k0 = ks * 8;
            uint32_t a0 = As[r0 + g][k0 + t];
            uint32_t a1 = As[r0 + g + 8][k0 + t];
            uint32_t a2 = As[r0 + g][k0 + t + 4];
            uint32_t a3 = As[r0 + g + 8][k0 + t + 4];
#pragma unroll
            for (int j = 0; j < 8; j++) {
                uint32_t b0 = Ws[j * 8 + g][k0 + t];
                uint32_t b1 = Ws[j * 8 + g][k0 + t + 4];
                mma_tf32(acc[j], a0, a1, a2, a3, b0, b1);
            }
        }
        __syncthreads();
    }
#pragma unroll
    for (int j = 0; j < 8; j++) {
        int col = j * 8 + 2 * t;
        float b0 = bias[col], b1 = bias[col + 1];
        int r1 = m0 + warp * 16 + g;
        if (r1 < NP) {
            float2 o = make_float2(fmaxf(acc[j][0] + b0, 0.f), fmaxf(acc[j][1] + b1, 0.f));
            *reinterpret_cast<float2*>(g_x + (size_t)r1 * H + col) = o;
        }
        int r2 = r1 + 8;
        if (r2 < NP) {
            float2 o = make_float2(fmaxf(acc[j][2] + b0, 0.f), fmaxf(acc[j][3] + b1, 0.f));
            *reinterpret_cast<float2*>(g_x + (size_t)r2 * H + col) = o;
        }
    }
}

// ---------------- CSR mean aggregation: hybrid 4/2/1 gather chains ------------
// Heavy-degree nodes (high ids, scheduled first) run 4 chains; light nodes
// (products, deg~6) take the 2-chain path identical to the round-5 behavior.
__global__ void __launch_bounds__(256) aggregate(int use_h) {
    int gw = (blockIdx.x * 256 + threadIdx.x) >> 5;
    if (gw >= NTOT) return;
    int node = NTOT - 1 - gw;     // heavy rows first
    int lane = threadIdx.x & 31;
    int start = g_rowstart[node];
    int deg = g_deg[node];
    const float* __restrict__ x = use_h ? g_h : g_x;
    int half = lane >> 4;
    int f = (lane & 15) * 4;
    float4 a0 = make_float4(0.f, 0.f, 0.f, 0.f);
    float4 a1 = make_float4(0.f, 0.f, 0.f, 0.f);
    float4 a2 = make_float4(0.f, 0.f, 0.f, 0.f);
    float4 a3 = make_float4(0.f, 0.f, 0.f, 0.f);
    int i = half;
    // 4-chain main loop for heavy nodes
    for (; i + 6 < deg; i += 8) {
        int s0 = __ldg(g_adj + start + i);
        int s1 = __ldg(g_adj + start + i + 2);
        int s2 = __ldg(g_adj + start + i + 4);
        int s3 = __ldg(g_adj + start + i + 6);
        float4 v0 = *reinterpret_cast<const float4*>(x + (size_t)s0 * H + f);
        float4 v1 = *reinterpret_cast<const float4*>(x + (size_t)s1 * H + f);
        float4 v2 = *reinterpret_cast<const float4*>(x + (size_t)s2 * H + f);
        float4 v3 = *reinterpret_cast<const float4*>(x + (size_t)s3 * H + f);
        a0.x += v0.x; a0.y += v0.y; a0.z += v0.z; a0.w += v0.w;
        a1.x += v1.x; a1.y += v1.y; a1.z += v1.z; a1.w += v1.w;
        a2.x += v2.x; a2.y += v2.y; a2.z += v2.z; a2.w += v2.w;
        a3.x += v3.x; a3.y += v3.y; a3.z += v3.z; a3.w += v3.w;
    }
    // 2-chain loop (covers light nodes, deg>=4)
    for (; i + 2 < deg; i += 4) {
        int s0 = __ldg(g_adj + start + i);
        int s1 = __ldg(g_adj + start + i + 2);
        float4 v0 = *reinterpret_cast<const float4*>(x + (size_t)s0 * H + f);
        float4 v1 = *reinterpret_cast<const float4*>(x + (size_t)s1 * H + f);
        a0.x += v0.x; a0.y += v0.y; a0.z += v0.z; a0.w += v0.w;
        a1.x += v1.x; a1.y += v1.y; a1.z += v1.z; a1.w += v1.w;
    }
    if (i < deg) {
        int s0 = __ldg(g_adj + start + i);
        float4 v0 = *reinterpret_cast<const float4*>(x + (size_t)s0 * H + f);
        a0.x += v0.x; a0.y += v0.y; a0.z += v0.z; a0.w += v0.w;
    }
    a0.x += a1.x + a2.x + a3.x;
    a0.y += a1.y + a2.y + a3.y;
    a0.z += a1.z + a2.z + a3.z;
    a0.w += a1.w + a2.w + a3.w;
    a0.x += __shfl_xor_sync(0xffffffffu, a0.x, 16);
    a0.y += __shfl_xor_sync(0xffffffffu, a0.y, 16);
    a0.z += __shfl_xor_sync(0xffffffffu, a0.z, 16);
    a0.w += __shfl_xor_sync(0xffffffffu, a0.w, 16);
    if (lane < 16) {
        float inv = 1.f / fmaxf((float)deg, 1.f);
        float4 o = make_float4(a0.x * inv, a0.y * inv, a0.z * inv, a0.w * inv);
        *reinterpret_cast<float4*>(g_agg + (size_t)node * H + f) = o;
    }
}

// ---------------- SAGE finalize via tf32 HMMA ---------------------------------
template <int NOUT, bool RELU, bool USEH>
__global__ void __launch_bounds__(256) finalize_tc(const float* __restrict__ Wr,
                                                   const float* __restrict__ Wl,
                                                   const float* __restrict__ bias,
                                                   float* __restrict__ outp) {
    constexpr int NT = NOUT / 8;
    __shared__ uint32_t As[128][20];
    __shared__ uint32_t Ws[NOUT][20];
    const int tid = threadIdx.x;
    const int m0 = blockIdx.x * 128;
    const int warp = tid >> 5, lane = tid & 31;
    const int g = lane >> 2, t = lane & 3;
    const float* xsrc = USEH ? g_h : g_x;
    float* out = (NOUT == H) ? g_h : outp;

    float acc[NT][4];
#pragma unroll
    for (int j = 0; j < NT; j++)
#pragma unroll
        for (int c = 0; c < 4; c++) acc[j][c] = 0.f;

    for (int kb = 0; kb < 2 * H; kb += 16) {
        const float* src = (kb < H) ? xsrc : g_agg;
        const float* W = (kb < H) ? Wr : Wl;
        const int kcol = kb & (H - 1);
#pragma unroll
        for (int q = 0; q < 2; q++) {
            int idx = tid + 256 * q;
            int row = idx >> 2, c4 = idx & 3;
            int rg = m0 + row; if (rg > NTOT - 1) rg = NTOT - 1;
            float4 v = *reinterpret_cast<const float4*>(src + (size_t)rg * H + kcol + c4 * 4);
            uint4 u = make_uint4(f2tf(v.x), f2tf(v.y), f2tf(v.z), f2tf(v.w));
            *reinterpret_cast<uint4*>(&As[row][c4 * 4]) = u;
        }
        if (tid < NOUT * 4) {
            int n = tid >> 2, c4 = tid & 3;
            float4 v = *reinterpret_cast<const float4*>(W + (size_t)n * H + kcol + c4 * 4);
            uint4 u = make_uint4(f2tf(v.x), f2tf(v.y), f2tf(v.z), f2tf(v.w));
            *reinterpret_cast<uint4*>(&Ws[n][c4 * 4]) = u;
        }
        __syncthreads();
        const int r0 = warp * 16;
#pragma unroll
        for (int ks = 0; ks < 2; ks++) {
            int k0 = ks * 8;
            uint32_t a0 = As[r0 + g][k0 + t];
            uint32_t a1 = As[r0 + g + 8][k0 + t];
            uint32_t a2 = As[r0 + g][k0 + t + 4];
            uint32_t a3 = As[r0 + g + 8][k0 + t + 4];
#pragma unroll
            for (int j = 0; j < NT; j++) {
                uint32_t b0 = Ws[j * 8 + g][k0 + t];
                uint32_t b1 = Ws[j * 8 + g][k0 + t + 4];
                mma_tf32(acc[j], a0, a1, a2, a3, b0, b1);
            }
        }
        __syncthreads();
    }
#pragma unroll
    for (int j = 0; j < NT; j++) {
        int col = j * 8 + 2 * t;
        float b0 = bias[col], b1 = bias[col + 1];
        int r1 = m0 + warp * 16 + g;
        if (r1 < NTOT) {
            float v0 = acc[j][0] + b0, v1 = acc[j][1] + b1;
            if (RELU) { v0 = fmaxf(v0, 0.f); v1 = fmaxf(v1, 0.f); }
            *reinterpret_cast<float2*>(out + (size_t)r1 * NOUT + col) = make_float2(v0, v1);
        }
        int r2 = r1 + 8;
        if (r2 < NTOT) {
            float v2 = acc[j][2] + b0, v3 = acc[j][3] + b1;
            if (RELU) { v2 = fmaxf(v2, 0.f); v3 = fmaxf(v3, 0.f); }
            *reinterpret_cast<float2*>(out + (size_t)r2 * NOUT + col) = make_float2(v2, v3);
        }
    }
}

// ---------------- launch -------------------------------------------------------
extern "C" void kernel_launch(void* const* d_in, const int* in_sizes, int n_in,
                              void* d_out, int out_size) {
    const float* x_product = (const float*)d_in[0];
    const int* pb_src = (const int*)d_in[1];
    const int* pb_dst = (const int*)d_in[2];
    const int* pc_src = (const int*)d_in[3];
    const int* pc_dst = (const int*)d_in[4];
    const int* ps_src = (const int*)d_in[5];
    const int* ps_dst = (const int*)d_in[6];
    const float* W_proj = (const float*)d_in[7];
    const float* b_proj = (const float*)d_in[8];
    const float* emb_brand = (const float*)d_in[9];
    const float* emb_cat = (const float*)d_in[10];
    const float* emb_shop = (const float*)d_in[11];
    const float* W1_l = (const float*)d_in[12];
    const float* b1_l = (const float*)d_in[13];
    const float* W1_r = (const float*)d_in[14];
    const float* W2_l = (const float*)d_in[15];
    const float* b2_l = (const float*)d_in[16];
    const float* W2_r = (const float*)d_in[17];
    float* out = (float*)d_out;

    const int nodeBlocks = (NTOT + 255) / 256;
    const int edgeBlocks = (3 * NE + 255) / 256;
    const int aggBlocks = (NTOT * 32 + 255) / 256;
    const int gemmBlocks = (NTOT + 127) / 128;

    static cudaStream_t s2 = nullptr;
    static cudaEvent_t evFork = nullptr, evJoin = nullptr;
    if (!s2) {
        cudaStreamCreateWithFlags(&s2, cudaStreamNonBlocking);
        cudaEventCreateWithFlags(&evFork, cudaEventDisableTiming);
        cudaEventCreateWithFlags(&evJoin, cudaEventDisableTiming);
    }

    // fork: CSR build on s2, feature assembly on main stream
    cudaEventRecord(evFork, 0);
    cudaStreamWaitEvent(s2, evFork, 0);

    zero_deg<<<nodeBlocks, 256, 0, s2>>>();
    hist_edges<<<edgeBlocks, 256, 0, s2>>>(pb_src, pb_dst, pc_src, pc_dst, ps_src, ps_dst);
    scanA<<<NBLK_SCAN, 256, 0, s2>>>();
    scanB<<<1, 512, 0, s2>>>();
    scanC<<<nodeBlocks, 256, 0, s2>>>();
    fill_csr<<<edgeBlocks, 256, 0, s2>>>(pb_src, pb_dst, pc_src, pc_dst, ps_src, ps_dst);
    cudaEventRecord(evJoin, s2);

    proj_tc<<<(NP + 127) / 128, 256>>>(x_product, W_proj, b_proj);
    copy_emb<<<((NB + NC + NS) * H / 4 + 255) / 256, 256>>>(emb_brand, emb_cat, emb_shop);

    cudaStreamWaitEvent(0, evJoin, 0);

    // --- layer 1 ---
    aggregate<<<aggBlocks, 256>>>(0);
    finalize_tc<64, true, false><<<gemmBlocks, 256>>>(W1_r, W1_l, b1_l, out);
    // --- layer 2 ---
    aggregate<<<aggBlocks, 256>>>(1);
    finalize_tc<32, false, true><<<gemmBlocks, 256>>>(W2_r, W2_l, b2_l, out);
}

// round 9
// speedup vs baseline: 1.1457x; 1.1457x over previous
#include <cuda_runtime.h>
#include <cstdint>

#define NP 500000
#define NB 20000
#define NC 5000
#define NS 2000
#define NTOT 527000
#define NE 500000
#define EDIR (3 * NE * 2)
#define H 64
#define FIN 384
#define NBCS (NTOT - NP)

#define SCAN_SPAN 2048
#define NBLK_SCAN ((NTOT + SCAN_SPAN - 1) / SCAN_SPAN)

// ---------------- scratch ----------------------------------------------------
__device__ float g_x[(size_t)NTOT * H];
__device__ float g_h[(size_t)NTOT * H];
__device__ float g_agg[(size_t)NTOT * H];    // layer-1 aggregation
__device__ float g_agg2[(size_t)NTOT * H];   // layer-2 aggregation (double buffer)
__device__ int   g_deg[NTOT];
__device__ int   g_rowstart[NTOT];
__device__ int   g_cursor[NTOT];
__device__ int   g_scaninc[NTOT];
__device__ int   g_blocksum[512];
__device__ int   g_adj[EDIR];

// ---------------- tf32 helpers ----------------------------------------------
__device__ __forceinline__ uint32_t f2tf(float x) {
    uint32_t r;
    asm("cvt.rna.tf32.f32 %0, %1;" : "=r"(r) : "f"(x));
    return r;
}
__device__ __forceinline__ void mma_tf32(float* d, uint32_t a0, uint32_t a1,
                                         uint32_t a2, uint32_t a3,
                                         uint32_t b0, uint32_t b1) {
    asm volatile(
        "mma.sync.aligned.m16n8k8.row.col.f32.tf32.tf32.f32 "
        "{%0,%1,%2,%3},{%4,%5,%6,%7},{%8,%9},{%0,%1,%2,%3};"
        : "+f"(d[0]), "+f"(d[1]), "+f"(d[2]), "+f"(d[3])
        : "r"(a0), "r"(a1), "r"(a2), "r"(a3), "r"(b0), "r"(b1));
}

// ---------------- CSR build ---------------------------------------------------
__global__ void __launch_bounds__(256) zero_deg() {
    int i = blockIdx.x * 256 + threadIdx.x;
    if (i < NTOT) g_deg[i] = 0;
}

__global__ void __launch_bounds__(256) hist_edges(
    const int* __restrict__ pb_src, const int* __restrict__ pb_dst,
    const int* __restrict__ pc_src, const int* __restrict__ pc_dst,
    const int* __restrict__ ps_src, const int* __restrict__ ps_dst) {
    int e = blockIdx.x * 256 + threadIdx.x;
    if (e >= 3 * NE) return;
    int t = e / NE, i = e - t * NE;
    const int* sp; const int* dp; int off;
    if (t == 0)      { sp = pb_src; dp = pb_dst; off = NP; }
    else if (t == 1) { sp = pc_src; dp = pc_dst; off = NP + NB; }
    else             { sp = ps_src; dp = ps_dst; off = NP + NB + NC; }
    int p = __ldg(sp + i);
    int o = __ldg(dp + i) + off;
    atomicAdd(&g_deg[p], 1);
    atomicAdd(&g_deg[o], 1);
}

__global__ void __launch_bounds__(256) scanA() {
    __shared__ int wsum[8];
    __shared__ int wpre[8];
    int tid = threadIdx.x, lane = tid & 31, wid = tid >> 5;
    int base = blockIdx.x * SCAN_SPAN + tid * 8;
    int v[8], run = 0;
#pragma unroll
    for (int t = 0; t < 8; t++) {
        int idx = base + t;
        int d = (idx < NTOT) ? g_deg[idx] : 0;
        run += d;
        v[t] = run;
    }
    int tot = run;
#pragma unroll
    for (int off = 1; off < 32; off <<= 1) {
        int n = __shfl_up_sync(0xffffffffu, tot, off);
        if (lane >= off) tot += n;
    }
    int wexcl = tot - run;
    if (lane == 31) wsum[wid] = tot;
    __syncthreads();
    if (tid < 8) {
        int s = wsum[tid];
        int r = s;
#pragma unroll
        for (int off = 1; off < 8; off <<= 1) {
            int n = __shfl_up_sync(0xffu, r, off);
            if (tid >= off) r += n;
        }
        wpre[tid] = r - s;
        if (tid == 7) g_blocksum[blockIdx.x] = r;
    }
    __syncthreads();
    int bexcl = wexcl + wpre[wid];
#pragma unroll
    for (int t = 0; t < 8; t++) {
        int idx = base + t;
        if (idx < NTOT) g_scaninc[idx] = v[t] + bexcl;
    }
}

__global__ void __launch_bounds__(512) scanB() {
    __shared__ int s[NBLK_SCAN];
    int tid = threadIdx.x;
    if (tid < NBLK_SCAN) s[tid] = g_blocksum[tid];
    __syncthreads();
    if (tid == 0) {
        int run = 0;
        for (int i = 0; i < NBLK_SCAN; i++) { int t = s[i]; s[i] = run; run += t; }
    }
    __syncthreads();
    if (tid < NBLK_SCAN) g_blocksum[tid] = s[tid];
}

__global__ void __launch_bounds__(256) scanC() {
    int i = blockIdx.x * 256 + threadIdx.x;
    if (i >= NTOT) return;
    int start = g_scaninc[i] + g_blocksum[i >> 11] - g_deg[i];
    g_rowstart[i] = start;
    g_cursor[i] = start;
}

__global__ void __launch_bounds__(256) fill_csr(
    const int* __restrict__ pb_src, const int* __restrict__ pb_dst,
    const int* __restrict__ pc_src, const int* __restrict__ pc_dst,
    const int* __restrict__ ps_src, const int* __restrict__ ps_dst) {
    int e = blockIdx.x * 256 + threadIdx.x;
    if (e >= 3 * NE) return;
    int t = e / NE, i = e - t * NE;
    const int* sp; const int* dp; int off;
    if (t == 0)      { sp = pb_src; dp = pb_dst; off = NP; }
    else if (t == 1) { sp = pc_src; dp = pc_dst; off = NP + NB; }
    else             { sp = ps_src; dp = ps_dst; off = NP + NB + NC; }
    int p = __ldg(sp + i);
    int o = __ldg(dp + i) + off;
    int pos = atomicAdd(&g_cursor[o], 1);
    g_adj[pos] = p;
    int pos2 = atomicAdd(&g_cursor[p], 1);
    g_adj[pos2] = o;
}

// ---------------- feature assembly --------------------------------------------
__global__ void __launch_bounds__(256) copy_emb(const float* __restrict__ eb,
                                                const float* __restrict__ ec,
                                                const float* __restrict__ es) {
    int i = blockIdx.x * 256 + threadIdx.x;
    const int tot = (NB + NC + NS) * H / 4;
    if (i >= tot) return;
    const int nb4 = NB * H / 4, nc4 = NC * H / 4;
    float4 v;
    if (i < nb4) v = reinterpret_cast<const float4*>(eb)[i];
    else if (i < nb4 + nc4) v = reinterpret_cast<const float4*>(ec)[i - nb4];
    else v = reinterpret_cast<const float4*>(es)[i - nb4 - nc4];
    reinterpret_cast<float4*>(g_x)[(size_t)NP * H / 4 + i] = v;
}

// ---------------- proj: relu(x_product @ W_proj^T + b) via tf32 HMMA ----------
__global__ void __launch_bounds__(256) proj_tc(const float* __restrict__ A,
                                               const float* __restrict__ W,
                                               const float* __restrict__ bias) {
    __shared__ uint32_t As[128][20];
    __shared__ uint32_t Ws[64][20];
    const int tid = threadIdx.x;
    const int m0 = blockIdx.x * 128;
    const int warp = tid >> 5, lane = tid & 31;
    const int g = lane >> 2, t = lane & 3;

    float acc[8][4];
#pragma unroll
    for (int j = 0; j < 8; j++)
#pragma unroll
        for (int c = 0; c < 4; c++) acc[j][c] = 0.f;

    for (int kb = 0; kb < FIN; kb += 16) {
#pragma unroll
        for (int q = 0; q < 2; q++) {
            int idx = tid + 256 * q;
            int row = idx >> 2, c4 = idx & 3;
            int rg = m0 + row; if (rg > NP - 1) rg = NP - 1;
            float4 v = *reinterpret_cast<const float4*>(A + (size_t)rg * FIN + kb + c4 * 4);
            uint4 u = make_uint4(f2tf(v.x), f2tf(v.y), f2tf(v.z), f2tf(v.w));
            *reinterpret_cast<uint4*>(&As[row][c4 * 4]) = u;
        }
        {
            int n = tid >> 2, c4 = tid & 3;
            float4 v = *reinterpret_cast<const float4*>(W + (size_t)n * FIN + kb + c4 * 4);
            uint4 u = make_uint4(f2tf(v.x), f2tf(v.y), f2tf(v.z), f2tf(v.w));
            *reinterpret_cast<uint4*>(&Ws[n][c4 * 4]) = u;
        }
        __syncthreads();
        const int r0 = warp * 16;
#pragma unroll
        for (int ks = 0; ks < 2; ks++) {
            int k0 = ks * 8;
            uint32_t a0 = As[r0 + g][k0 + t];
            uint32_t a1 = As[r0 + g + 8][k0 + t];
            uint32_t a2 = As[r0 + g][k0 + t + 4];
            uint32_t a3 = As[r0 + g + 8][k0 + t + 4];
#pragma unroll
            for (int j = 0; j < 8; j++) {
                uint32_t b0 = Ws[j * 8 + g][k0 + t];
                uint32_t b1 = Ws[j * 8 + g][k0 + t + 4];
                mma_tf32(acc[j], a0, a1, a2, a3, b0, b1);
            }
        }
        __syncthreads();
    }
#pragma unroll
    for (int j = 0; j < 8; j++) {
        int col = j * 8 + 2 * t;
        float b0 = bias[col], b1 = bias[col + 1];
        int r1 = m0 + warp * 16 + g;
        if (r1 < NP) {
            float2 o = make_float2(fmaxf(acc[j][0] + b0, 0.f), fmaxf(acc[j][1] + b1, 0.f));
            *reinterpret_cast<float2*>(g_x + (size_t)r1 * H + col) = o;
        }
        int r2 = r1 + 8;
        if (r2 < NP) {
            float2 o = make_float2(fmaxf(acc[j][2] + b0, 0.f), fmaxf(acc[j][3] + b1, 0.f));
            *reinterpret_cast<float2*>(g_x + (size_t)r2 * H + col) = o;
        }
    }
}

// ---------------- CSR mean aggregation (range + buffer parameterized) ---------
// layer=0: read g_x, write g_agg. layer=1: read g_h, write g_agg2.
__global__ void __launch_bounds__(256) aggregate(int layer, int base, int n) {
    int gw = (blockIdx.x * 256 + threadIdx.x) >> 5;
    if (gw >= n) return;
    int node = base + n - 1 - gw;  // heavy (high-id) rows first
    int lane = threadIdx.x & 31;
    int start = g_rowstart[node];
    int deg = g_deg[node];
    const float* __restrict__ x = layer ? g_h : g_x;
    float* __restrict__ dst = layer ? g_agg2 : g_agg;
    int half = lane >> 4;
    int f = (lane & 15) * 4;
    float4 acc0 = make_float4(0.f, 0.f, 0.f, 0.f);
    float4 acc1 = make_float4(0.f, 0.f, 0.f, 0.f);
    int i = half;
    for (; i + 2 < deg; i += 4) {
        int s0 = __ldg(g_adj + start + i);
        int s1 = __ldg(g_adj + start + i + 2);
        float4 v0 = *reinterpret_cast<const float4*>(x + (size_t)s0 * H + f);
        float4 v1 = *reinterpret_cast<const float4*>(x + (size_t)s1 * H + f);
        acc0.x += v0.x; acc0.y += v0.y; acc0.z += v0.z; acc0.w += v0.w;
        acc1.x += v1.x; acc1.y += v1.y; acc1.z += v1.z; acc1.w += v1.w;
    }
    if (i < deg) {
        int s0 = __ldg(g_adj + start + i);
        float4 v0 = *reinterpret_cast<const float4*>(x + (size_t)s0 * H + f);
        acc0.x += v0.x; acc0.y += v0.y; acc0.z += v0.z; acc0.w += v0.w;
    }
    acc0.x += acc1.x; acc0.y += acc1.y; acc0.z += acc1.z; acc0.w += acc1.w;
    acc0.x += __shfl_xor_sync(0xffffffffu, acc0.x, 16);
    acc0.y += __shfl_xor_sync(0xffffffffu, acc0.y, 16);
    acc0.z += __shfl_xor_sync(0xffffffffu, acc0.z, 16);
    acc0.w += __shfl_xor_sync(0xffffffffu, acc0.w, 16);
    if (lane < 16) {
        float inv = 1.f / fmaxf((float)deg, 1.f);
        float4 o = make_float4(acc0.x * inv, acc0.y * inv, acc0.z * inv, acc0.w * inv);
        *reinterpret_cast<float4*>(dst + (size_t)node * H + f) = o;
    }
}

// ---------------- SAGE finalize via tf32 HMMA (block-offset parameterized) ----
// USEH=false: layer 1 (x=g_x, agg=g_agg). USEH=true: layer 2 (x=g_h, agg=g_agg2).
template <int NOUT, bool RELU, bool USEH>
__global__ void __launch_bounds__(256) finalize_tc(const float* __restrict__ Wr,
                                                   const float* __restrict__ Wl,
                                                   const float* __restrict__ bias,
                                                   float* __restrict__ outp,
                                                   int blockOff) {
    constexpr int NT = NOUT / 8;
    __shared__ uint32_t As[128][20];
    __shared__ uint32_t Ws[NOUT][20];
    const int tid = threadIdx.x;
    const int m0 = (blockIdx.x + blockOff) * 128;
    const int warp = tid >> 5, lane = tid & 31;
    const int g = lane >> 2, t = lane & 3;
    const float* xsrc = USEH ? g_h : g_x;
    const float* aggsrc = USEH ? g_agg2 : g_agg;
    float* out = (NOUT == H) ? g_h : outp;

    float acc[NT][4];
#pragma unroll
    for (int j = 0; j < NT; j++)
#pragma unroll
        for (int c = 0; c < 4; c++) acc[j][c] = 0.f;

    for (int kb = 0; kb < 2 * H; kb += 16) {
        const float* src = (kb < H) ? xsrc : aggsrc;
        const float* W = (kb < H) ? Wr : Wl;
        const int kcol = kb & (H - 1);
#pragma unroll
        for (int q = 0; q < 2; q++) {
            int idx = tid + 256 * q;
            int row = idx >> 2, c4 = idx & 3;
            int rg = m0 + row; if (rg > NTOT - 1) rg = NTOT - 1;
            float4 v = *reinterpret_cast<const float4*>(src + (size_t)rg * H + kcol + c4 * 4);
            uint4 u = make_uint4(f2tf(v.x), f2tf(v.y), f2tf(v.z), f2tf(v.w));
            *reinterpret_cast<uint4*>(&As[row][c4 * 4]) = u;
        }
        if (tid < NOUT * 4) {
            int n = tid >> 2, c4 = tid & 3;
            float4 v = *reinterpret_cast<const float4*>(W + (size_t)n * H + kcol + c4 * 4);
            uint4 u = make_uint4(f2tf(v.x), f2tf(v.y), f2tf(v.z), f2tf(v.w));
            *reinterpret_cast<uint4*>(&Ws[n][c4 * 4]) = u;
        }
        __syncthreads();
        const int r0 = warp * 16;
#pragma unroll
        for (int ks = 0; ks < 2; ks++) {
            int k0 = ks * 8;
            uint32_t a0 = As[r0 + g][k0 + t];
            uint32_t a1 = As[r0 + g + 8][k0 + t];
            uint32_t a2 = As[r0 + g][k0 + t + 4];
            uint32_t a3 = As[r0 + g + 8][k0 + t + 4];
#pragma unroll
            for (int j = 0; j < NT; j++) {
                uint32_t b0 = Ws[j * 8 + g][k0 + t];
                uint32_t b1 = Ws[j * 8 + g][k0 + t + 4];
                mma_tf32(acc[j], a0, a1, a2, a3, b0, b1);
            }
        }
        __syncthreads();
    }
#pragma unroll
    for (int j = 0; j < NT; j++) {
        int col = j * 8 + 2 * t;
        float b0 = bias[col], b1 = bias[col + 1];
        int r1 = m0 + warp * 16 + g;
        if (r1 < NTOT) {
            float v0 = acc[j][0] + b0, v1 = acc[j][1] + b1;
            if (RELU) { v0 = fmaxf(v0, 0.f); v1 = fmaxf(v1, 0.f); }
            *reinterpret_cast<float2*>(out + (size_t)r1 * NOUT + col) = make_float2(v0, v1);
        }
        int r2 = r1 + 8;
        if (r2 < NTOT) {
            float v2 = acc[j][2] + b0, v3 = acc[j][3] + b1;
            if (RELU) { v2 = fmaxf(v2, 0.f); v3 = fmaxf(v3, 0.f); }
            *reinterpret_cast<float2*>(out + (size_t)r2 * NOUT + col) = make_float2(v2, v3);
        }
    }
}

// ---------------- launch -------------------------------------------------------
extern "C" void kernel_launch(void* const* d_in, const int* in_sizes, int n_in,
                              void* d_out, int out_size) {
    const float* x_product = (const float*)d_in[0];
    const int* pb_src = (const int*)d_in[1];
    const int* pb_dst = (const int*)d_in[2];
    const int* pc_src = (const int*)d_in[3];
    const int* pc_dst = (const int*)d_in[4];
    const int* ps_src = (const int*)d_in[5];
    const int* ps_dst = (const int*)d_in[6];
    const float* W_proj = (const float*)d_in[7];
    const float* b_proj = (const float*)d_in[8];
    const float* emb_brand = (const float*)d_in[9];
    const float* emb_cat = (const float*)d_in[10];
    const float* emb_shop = (const float*)d_in[11];
    const float* W1_l = (const float*)d_in[12];
    const float* b1_l = (const float*)d_in[13];
    const float* W1_r = (const float*)d_in[14];
    const float* W2_l = (const float*)d_in[15];
    const float* b2_l = (const float*)d_in[16];
    const float* W2_r = (const float*)d_in[17];
    float* out = (float*)d_out;

    const int nodeBlocks = (NTOT + 255) / 256;
    const int edgeBlocks = (3 * NE + 255) / 256;
    const int gemmBlocks = (NTOT + 127) / 128;      // 4118
    const int loBlocks = NP / 128;                   // 3906 (rows 0..499967)
    const int hiBlocks = gemmBlocks - loBlocks;      // 212  (rows 499968..NTOT)
    const int aggProdBlocks = (NP * 32 + 255) / 256;
    const int aggBcsBlocks = (NBCS * 32 + 255) / 256;

    static cudaStream_t s2 = nullptr;
    static cudaEvent_t evFork = nullptr, evCopy = nullptr, evCsr = nullptr,
                       evP0 = nullptr, evH = nullptr, evP1 = nullptr;
    if (!s2) {
        cudaStreamCreateWithFlags(&s2, cudaStreamNonBlocking);
        cudaEventCreateWithFlags(&evFork, cudaEventDisableTiming);
        cudaEventCreateWithFlags(&evCopy, cudaEventDisableTiming);
        cudaEventCreateWithFlags(&evCsr, cudaEventDisableTiming);
        cudaEventCreateWithFlags(&evP0, cudaEventDisableTiming);
        cudaEventCreateWithFlags(&evH, cudaEventDisableTiming);
        cudaEventCreateWithFlags(&evP1, cudaEventDisableTiming);
    }

    // ---- fork: CSR build on s2; assembly on main ----
    cudaEventRecord(evFork, 0);
    cudaStreamWaitEvent(s2, evFork, 0);

    zero_deg<<<nodeBlocks, 256, 0, s2>>>();
    hist_edges<<<edgeBlocks, 256, 0, s2>>>(pb_src, pb_dst, pc_src, pc_dst, ps_src, ps_dst);
    scanA<<<NBLK_SCAN, 256, 0, s2>>>();
    scanB<<<1, 512, 0, s2>>>();
    scanC<<<nodeBlocks, 256, 0, s2>>>();
    fill_csr<<<edgeBlocks, 256, 0, s2>>>(pb_src, pb_dst, pc_src, pc_dst, ps_src, ps_dst);
    cudaEventRecord(evCsr, s2);

    copy_emb<<<((NB + NC + NS) * H / 4 + 255) / 256, 256>>>(emb_brand, emb_cat, emb_shop);
    cudaEventRecord(evCopy, 0);
    proj_tc<<<(NP + 127) / 128, 256>>>(x_product, W_proj, b_proj);

    // agg0 product side: gathers only bcs rows of g_x (CSR in-order on s2,
    // copy_emb via event) -> overlaps with proj on main. Writes g_agg[0..NP).
    cudaStreamWaitEvent(s2, evCopy, 0);
    aggregate<<<aggProdBlocks, 256, 0, s2>>>(0, 0, NP);
    cudaEventRecord(evP0, s2);

    // agg0 bcs side: gathers product rows of g_x (needs proj; main in-order) + CSR
    cudaStreamWaitEvent(0, evCsr, 0);
    aggregate<<<aggBcsBlocks, 256, 0, 0>>>(0, NP, NBCS);

    // ---- layer 1 finalize: hi rows first (feeds agg1_prod), then lo rows ----
    cudaStreamWaitEvent(0, evP0, 0);   // hi tile spans 32 product rows too
    finalize_tc<64, true, false><<<hiBlocks, 256>>>(W1_r, W1_l, b1_l, out, loBlocks);
    cudaEventRecord(evH, 0);
    finalize_tc<64, true, false><<<loBlocks, 256>>>(W1_r, W1_l, b1_l, out, 0);

    // agg1 product side: reads bcs rows of g_h (fin1_hi done via evH),
    // writes g_agg2[0..NP) -- no aliasing with fin1_lo's g_agg reads.
    cudaStreamWaitEvent(s2, evH, 0);
    aggregate<<<aggProdBlocks, 256, 0, s2>>>(1, 0, NP);
    cudaEventRecord(evP1, s2);

    // agg1 bcs side: reads product rows of g_h (fin1_lo; main in-order), writes g_agg2
    aggregate<<<aggBcsBlocks, 256, 0, 0>>>(1, NP, NBCS);

    // ---- layer 2 finalize ----
    cudaStreamWaitEvent(0, evP1, 0);
    finalize_tc<32, false, true><<<gemmBlocks, 256>>>(W2_r, W2_l, b2_l, out, 0);
}

// round 10
// speedup vs baseline: 1.1556x; 1.0086x over previous
#include <cuda_runtime.h>
#include <cstdint>

#define NP 500000
#define NB 20000
#define NC 5000
#define NS 2000
#define NTOT 527000
#define NE 500000
#define EDIR (3 * NE * 2)
#define H 64
#define O 32
#define FIN 384

#define SCAN_SPAN 2048
#define NBLK_SCAN ((NTOT + SCAN_SPAN - 1) / SCAN_SPAN)

// ---------------- scratch ----------------------------------------------------
__device__ float g_x[(size_t)NTOT * H];
__device__ float g_h[(size_t)NTOT * H];
__device__ float g_agg[(size_t)NTOT * H];    // layer-1 mean of x  (64-dim)
__device__ float g_y[(size_t)NTOT * O];      // y = relu(h) @ W2_l^T (32-dim)
__device__ float g_aggy[(size_t)NTOT * O];   // layer-2 mean of y  (32-dim)
__device__ int   g_deg[NTOT];
__device__ int   g_rowstart[NTOT];
__device__ int   g_cursor[NTOT];
__device__ int   g_scaninc[NTOT];
__device__ int   g_blocksum[512];
__device__ int   g_adj[EDIR];

// ---------------- tf32 helpers ----------------------------------------------
__device__ __forceinline__ uint32_t f2tf(float x) {
    uint32_t r;
    asm("cvt.rna.tf32.f32 %0, %1;" : "=r"(r) : "f"(x));
    return r;
}
__device__ __forceinline__ void mma_tf32(float* d, uint32_t a0, uint32_t a1,
                                         uint32_t a2, uint32_t a3,
                                         uint32_t b0, uint32_t b1) {
    asm volatile(
        "mma.sync.aligned.m16n8k8.row.col.f32.tf32.tf32.f32 "
        "{%0,%1,%2,%3},{%4,%5,%6,%7},{%8,%9},{%0,%1,%2,%3};"
        : "+f"(d[0]), "+f"(d[1]), "+f"(d[2]), "+f"(d[3])
        : "r"(a0), "r"(a1), "r"(a2), "r"(a3), "r"(b0), "r"(b1));
}

// ---------------- CSR build ---------------------------------------------------
__global__ void __launch_bounds__(256) zero_deg() {
    int i = blockIdx.x * 256 + threadIdx.x;
    if (i < NTOT) g_deg[i] = 0;
}

__global__ void __launch_bounds__(256) hist_edges(
    const int* __restrict__ pb_src, const int* __restrict__ pb_dst,
    const int* __restrict__ pc_src, const int* __restrict__ pc_dst,
    const int* __restrict__ ps_src, const int* __restrict__ ps_dst) {
    int e = blockIdx.x * 256 + threadIdx.x;
    if (e >= 3 * NE) return;
    int t = e / NE, i = e - t * NE;
    const int* sp; const int* dp; int off;
    if (t == 0)      { sp = pb_src; dp = pb_dst; off = NP; }
    else if (t == 1) { sp = pc_src; dp = pc_dst; off = NP + NB; }
    else             { sp = ps_src; dp = ps_dst; off = NP + NB + NC; }
    int p = __ldg(sp + i);
    int o = __ldg(dp + i) + off;
    atomicAdd(&g_deg[p], 1);
    atomicAdd(&g_deg[o], 1);
}

__global__ void __launch_bounds__(256) scanA() {
    __shared__ int wsum[8];
    __shared__ int wpre[8];
    int tid = threadIdx.x, lane = tid & 31, wid = tid >> 5;
    int base = blockIdx.x * SCAN_SPAN + tid * 8;
    int v[8], run = 0;
#pragma unroll
    for (int t = 0; t < 8; t++) {
        int idx = base + t;
        int d = (idx < NTOT) ? g_deg[idx] : 0;
        run += d;
        v[t] = run;
    }
    int tot = run;
#pragma unroll
    for (int off = 1; off < 32; off <<= 1) {
        int n = __shfl_up_sync(0xffffffffu, tot, off);
        if (lane >= off) tot += n;
    }
    int wexcl = tot - run;
    if (lane == 31) wsum[wid] = tot;
    __syncthreads();
    if (tid < 8) {
        int s = wsum[tid];
        int r = s;
#pragma unroll
        for (int off = 1; off < 8; off <<= 1) {
            int n = __shfl_up_sync(0xffu, r, off);
            if (tid >= off) r += n;
        }
        wpre[tid] = r - s;
        if (tid == 7) g_blocksum[blockIdx.x] = r;
    }
    __syncthreads();
    int bexcl = wexcl + wpre[wid];
#pragma unroll
    for (int t = 0; t < 8; t++) {
        int idx = base + t;
        if (idx < NTOT) g_scaninc[idx] = v[t] + bexcl;
    }
}

__global__ void __launch_bounds__(512) scanB() {
    __shared__ int s[NBLK_SCAN];
    int tid = threadIdx.x;
    if (tid < NBLK_SCAN) s[tid] = g_blocksum[tid];
    __syncthreads();
    if (tid == 0) {
        int run = 0;
        for (int i = 0; i < NBLK_SCAN; i++) { int t = s[i]; s[i] = run; run += t; }
    }
    __syncthreads();
    if (tid < NBLK_SCAN) g_blocksum[tid] = s[tid];
}

__global__ void __launch_bounds__(256) scanC() {
    int i = blockIdx.x * 256 + threadIdx.x;
    if (i >= NTOT) return;
    int start = g_scaninc[i] + g_blocksum[i >> 11] - g_deg[i];
    g_rowstart[i] = start;
    g_cursor[i] = start;
}

__global__ void __launch_bounds__(256) fill_csr(
    const int* __restrict__ pb_src, const int* __restrict__ pb_dst,
    const int* __restrict__ pc_src, const int* __restrict__ pc_dst,
    const int* __restrict__ ps_src, const int* __restrict__ ps_dst) {
    int e = blockIdx.x * 256 + threadIdx.x;
    if (e >= 3 * NE) return;
    int t = e / NE, i = e - t * NE;
    const int* sp; const int* dp; int off;
    if (t == 0)      { sp = pb_src; dp = pb_dst; off = NP; }
    else if (t == 1) { sp = pc_src; dp = pc_dst; off = NP + NB; }
    else             { sp = ps_src; dp = ps_dst; off = NP + NB + NC; }
    int p = __ldg(sp + i);
    int o = __ldg(dp + i) + off;
    int pos = atomicAdd(&g_cursor[o], 1);
    g_adj[pos] = p;
    int pos2 = atomicAdd(&g_cursor[p], 1);
    g_adj[pos2] = o;
}

// ---------------- feature assembly --------------------------------------------
__global__ void __launch_bounds__(256) copy_emb(const float* __restrict__ eb,
                                                const float* __restrict__ ec,
                                                const float* __restrict__ es) {
    int i = blockIdx.x * 256 + threadIdx.x;
    const int tot = (NB + NC + NS) * H / 4;
    if (i >= tot) return;
    const int nb4 = NB * H / 4, nc4 = NC * H / 4;
    float4 v;
    if (i < nb4) v = reinterpret_cast<const float4*>(eb)[i];
    else if (i < nb4 + nc4) v = reinterpret_cast<const float4*>(ec)[i - nb4];
    else v = reinterpret_cast<const float4*>(es)[i - nb4 - nc4];
    reinterpret_cast<float4*>(g_x)[(size_t)NP * H / 4 + i] = v;
}

// ---------------- proj: relu(x_product @ W_proj^T + b) via tf32 HMMA ----------
__global__ void __launch_bounds__(256) proj_tc(const float* __restrict__ A,
                                               const float* __restrict__ W,
                                               const float* __restrict__ bias) {
    __shared__ uint32_t As[128][20];
    __shared__ uint32_t Ws[64][20];
    const int tid = threadIdx.x;
    const int m0 = blockIdx.x * 128;
    const int warp = tid >> 5, lane = tid & 31;
    const int g = lane >> 2, t = lane & 3;

    float acc[8][4];
#pragma unroll
    for (int j = 0; j < 8; j++)
#pragma unroll
        for (int c = 0; c < 4; c++) acc[j][c] = 0.f;

    for (int kb = 0; kb < FIN; kb += 16) {
#pragma unroll
        for (int q = 0; q < 2; q++) {
            int idx = tid + 256 * q;
            int row = idx >> 2, c4 = idx & 3;
            int rg = m0 + row; if (rg > NP - 1) rg = NP - 1;
            float4 v = *reinterpret_cast<const float4*>(A + (size_t)rg * FIN + kb + c4 * 4);
            uint4 u = make_uint4(f2tf(v.x), f2tf(v.y), f2tf(v.z), f2tf(v.w));
            *reinterpret_cast<uint4*>(&As[row][c4 * 4]) = u;
        }
        {
            int n = tid >> 2, c4 = tid & 3;
            float4 v = *reinterpret_cast<const float4*>(W + (size_t)n * FIN + kb + c4 * 4);
            uint4 u = make_uint4(f2tf(v.x), f2tf(v.y), f2tf(v.z), f2tf(v.w));
            *reinterpret_cast<uint4*>(&Ws[n][c4 * 4]) = u;
        }
        __syncthreads();
        const int r0 = warp * 16;
#pragma unroll
        for (int ks = 0; ks < 2; ks++) {
            int k0 = ks * 8;
            uint32_t a0 = As[r0 + g][k0 + t];
            uint32_t a1 = As[r0 + g + 8][k0 + t];
            uint32_t a2 = As[r0 + g][k0 + t + 4];
            uint32_t a3 = As[r0 + g + 8][k0 + t + 4];
#pragma unroll
            for (int j = 0; j < 8; j++) {
                uint32_t b0 = Ws[j * 8 + g][k0 + t];
                uint32_t b1 = Ws[j * 8 + g][k0 + t + 4];
                mma_tf32(acc[j], a0, a1, a2, a3, b0, b1);
            }
        }
        __syncthreads();
    }
#pragma unroll
    for (int j = 0; j < 8; j++) {
        int col = j * 8 + 2 * t;
        float b0 = bias[col], b1 = bias[col + 1];
        int r1 = m0 + warp * 16 + g;
        if (r1 < NP) {
            float2 o = make_float2(fmaxf(acc[j][0] + b0, 0.f), fmaxf(acc[j][1] + b1, 0.f));
            *reinterpret_cast<float2*>(g_x + (size_t)r1 * H + col) = o;
        }
        int r2 = r1 + 8;
        if (r2 < NP) {
            float2 o = make_float2(fmaxf(acc[j][2] + b0, 0.f), fmaxf(acc[j][3] + b1, 0.f));
            *reinterpret_cast<float2*>(g_x + (size_t)r2 * H + col) = o;
        }
    }
}

// ---------------- layer-1 aggregation: mean of x (64-dim), round-5 body -------
__global__ void __launch_bounds__(256) aggregate64() {
    int gw = (blockIdx.x * 256 + threadIdx.x) >> 5;
    if (gw >= NTOT) return;
    int node = NTOT - 1 - gw;     // heavy (high-id) rows first
    int lane = threadIdx.x & 31;
    int start = g_rowstart[node];
    int deg = g_deg[node];
    int half = lane >> 4;
    int f = (lane & 15) * 4;
    float4 acc0 = make_float4(0.f, 0.f, 0.f, 0.f);
    float4 acc1 = make_float4(0.f, 0.f, 0.f, 0.f);
    int i = half;
    for (; i + 2 < deg; i += 4) {
        int s0 = __ldg(g_adj + start + i);
        int s1 = __ldg(g_adj + start + i + 2);
        float4 v0 = *reinterpret_cast<const float4*>(g_x + (size_t)s0 * H + f);
        float4 v1 = *reinterpret_cast<const float4*>(g_x + (size_t)s1 * H + f);
        acc0.x += v0.x; acc0.y += v0.y; acc0.z += v0.z; acc0.w += v0.w;
        acc1.x += v1.x; acc1.y += v1.y; acc1.z += v1.z; acc1.w += v1.w;
    }
    if (i < deg) {
        int s0 = __ldg(g_adj + start + i);
        float4 v0 = *reinterpret_cast<const float4*>(g_x + (size_t)s0 * H + f);
        acc0.x += v0.x; acc0.y += v0.y; acc0.z += v0.z; acc0.w += v0.w;
    }
    acc0.x += acc1.x; acc0.y += acc1.y; acc0.z += acc1.z; acc0.w += acc1.w;
    acc0.x += __shfl_xor_sync(0xffffffffu, acc0.x, 16);
    acc0.y += __shfl_xor_sync(0xffffffffu, acc0.y, 16);
    acc0.z += __shfl_xor_sync(0xffffffffu, acc0.z, 16);
    acc0.w += __shfl_xor_sync(0xffffffffu, acc0.w, 16);
    if (lane < 16) {
        float inv = 1.f / fmaxf((float)deg, 1.f);
        float4 o = make_float4(acc0.x * inv, acc0.y * inv, acc0.z * inv, acc0.w * inv);
        *reinterpret_cast<float4*>(g_agg + (size_t)node * H + f) = o;
    }
}

// ---------------- layer-2 aggregation: mean of y (32-dim), quarter-warps ------
// Each quarter (8 lanes x float4 = 128B row) owns i = q (mod 4); 2 chains/thread.
__global__ void __launch_bounds__(256) aggregate32() {
    int gw = (blockIdx.x * 256 + threadIdx.x) >> 5;
    if (gw >= NTOT) return;
    int node = NTOT - 1 - gw;
    int lane = threadIdx.x & 31;
    int start = g_rowstart[node];
    int deg = g_deg[node];
    int q = lane >> 3;            // quarter 0..3
    int f = (lane & 7) * 4;       // feature offset within 32
    float4 acc0 = make_float4(0.f, 0.f, 0.f, 0.f);
    float4 acc1 = make_float4(0.f, 0.f, 0.f, 0.f);
    int i = q;
    for (; i + 4 < deg; i += 8) {
        int s0 = __ldg(g_adj + start + i);
        int s1 = __ldg(g_adj + start + i + 4);
        float4 v0 = *reinterpret_cast<const float4*>(g_y + (size_t)s0 * O + f);
        float4 v1 = *reinterpret_cast<const float4*>(g_y + (size_t)s1 * O + f);
        acc0.x += v0.x; acc0.y += v0.y; acc0.z += v0.z; acc0.w += v0.w;
        acc1.x += v1.x; acc1.y += v1.y; acc1.z += v1.z; acc1.w += v1.w;
    }
    if (i < deg) {
        int s0 = __ldg(g_adj + start + i);
        float4 v0 = *reinterpret_cast<const float4*>(g_y + (size_t)s0 * O + f);
        acc0.x += v0.x; acc0.y += v0.y; acc0.z += v0.z; acc0.w += v0.w;
    }
    acc0.x += acc1.x; acc0.y += acc1.y; acc0.z += acc1.z; acc0.w += acc1.w;
    acc0.x += __shfl_xor_sync(0xffffffffu, acc0.x, 8);
    acc0.y += __shfl_xor_sync(0xffffffffu, acc0.y, 8);
    acc0.z += __shfl_xor_sync(0xffffffffu, acc0.z, 8);
    acc0.w += __shfl_xor_sync(0xffffffffu, acc0.w, 8);
    acc0.x += __shfl_xor_sync(0xffffffffu, acc0.x, 16);
    acc0.y += __shfl_xor_sync(0xffffffffu, acc0.y, 16);
    acc0.z += __shfl_xor_sync(0xffffffffu, acc0.z, 16);
    acc0.w += __shfl_xor_sync(0xffffffffu, acc0.w, 16);
    if (lane < 8) {
        float inv = 1.f / fmaxf((float)deg, 1.f);
        float4 o = make_float4(acc0.x * inv, acc0.y * inv, acc0.z * inv, acc0.w * inv);
        *reinterpret_cast<float4*>(g_aggy + (size_t)node * O + f) = o;
    }
}

// ---------------- fin1: h = relu(x@W1r^T + agg@W1l^T + b1); y = h@W2l^T -------
// Dynamic smem: As[128][20] | Ws[64][20] | Hs[128][68]  (50176 bytes)
__global__ void __launch_bounds__(256) fin1_tc(const float* __restrict__ W1r,
                                               const float* __restrict__ W1l,
                                               const float* __restrict__ b1,
                                               const float* __restrict__ W2l) {
    extern __shared__ uint32_t sm[];
    uint32_t (*As)[20] = reinterpret_cast<uint32_t(*)[20]>(sm);
    uint32_t (*Ws)[20] = reinterpret_cast<uint32_t(*)[20]>(sm + 128 * 20);
    uint32_t (*Hs)[68] = reinterpret_cast<uint32_t(*)[68]>(sm + 128 * 20 + 64 * 20);
    const int tid = threadIdx.x;
    const int m0 = blockIdx.x * 128;
    const int warp = tid >> 5, lane = tid & 31;
    const int g = lane >> 2, t = lane & 3;
    const int r0 = warp * 16;

    float acc[8][4];
#pragma unroll
    for (int j = 0; j < 8; j++)
#pragma unroll
        for (int c = 0; c < 4; c++) acc[j][c] = 0.f;

    // ---- GEMM 1: virtual K=128 over {x,W1r} then {agg,W1l} ----
    for (int kb = 0; kb < 2 * H; kb += 16) {
        const float* src = (kb < H) ? g_x : g_agg;
        const float* W = (kb < H) ? W1r : W1l;
        const int kcol = kb & (H - 1);
#pragma unroll
        for (int q = 0; q < 2; q++) {
            int idx = tid + 256 * q;
            int row = idx >> 2, c4 = idx & 3;
            int rg = m0 + row; if (rg > NTOT - 1) rg = NTOT - 1;
            float4 v = *reinterpret_cast<const float4*>(src + (size_t)rg * H + kcol + c4 * 4);
            uint4 u = make_uint4(f2tf(v.x), f2tf(v.y), f2tf(v.z), f2tf(v.w));
            *reinterpret_cast<uint4*>(&As[row][c4 * 4]) = u;
        }
        {
            int n = tid >> 2, c4 = tid & 3;
            float4 v = *reinterpret_cast<const float4*>(W + (size_t)n * H + kcol + c4 * 4);
            uint4 u = make_uint4(f2tf(v.x), f2tf(v.y), f2tf(v.z), f2tf(v.w));
            *reinterpret_cast<uint4*>(&Ws[n][c4 * 4]) = u;
        }
        __syncthreads();
#pragma unroll
        for (int ks = 0; ks < 2; ks++) {
            int k0 = ks * 8;
            uint32_t a0 = As[r0 + g][k0 + t];
            uint32_t a1 = As[r0 + g + 8][k0 + t];
            uint32_t a2 = As[r0 + g][k0 + t + 4];
            uint32_t a3 = As[r0 + g + 8][k0 + t + 4];
#pragma unroll
            for (int j = 0; j < 8; j++) {
                uint32_t b0 = Ws[j * 8 + g][k0 + t];
                uint32_t b1 = Ws[j * 8 + g][k0 + t + 4];
                mma_tf32(acc[j], a0, a1, a2, a3, b0, b1);
            }
        }
        __syncthreads();
    }
    // ---- epilogue 1: relu -> g_h and Hs (tf32) ----
#pragma unroll
    for (int j = 0; j < 8; j++) {
        int col = j * 8 + 2 * t;
        float b0 = b1[col], bb1 = b1[col + 1];
        int rl1 = r0 + g, rl2 = r0 + g + 8;
        int r1 = m0 + rl1, r2 = m0 + rl2;
        float v0 = fmaxf(acc[j][0] + b0, 0.f), v1 = fmaxf(acc[j][1] + bb1, 0.f);
        float v2 = fmaxf(acc[j][2] + b0, 0.f), v3 = fmaxf(acc[j][3] + bb1, 0.f);
        Hs[rl1][col] = f2tf(v0); Hs[rl1][col + 1] = f2tf(v1);
        Hs[rl2][col] = f2tf(v2); Hs[rl2][col + 1] = f2tf(v3);
        if (r1 < NTOT)
            *reinterpret_cast<float2*>(g_h + (size_t)r1 * H + col) = make_float2(v0, v1);
        if (r2 < NTOT)
            *reinterpret_cast<float2*>(g_h + (size_t)r2 * H + col) = make_float2(v2, v3);
    }
    __syncthreads();
    // ---- GEMM 2: y = h @ W2l^T (K=64, N=32) ----
    float acc2[4][4];
#pragma unroll
    for (int j = 0; j < 4; j++)
#pragma unroll
        for (int c = 0; c < 4; c++) acc2[j][c] = 0.f;

    for (int kb = 0; kb < H; kb += 16) {
        if (tid < O * 4) {
            int n = tid >> 2, c4 = tid & 3;
            float4 v = *reinterpret_cast<const float4*>(W2l + (size_t)n * H + kb + c4 * 4);
            uint4 u = make_uint4(f2tf(v.x), f2tf(v.y), f2tf(v.z), f2tf(v.w));
            *reinterpret_cast<uint4*>(&Ws[n][c4 * 4]) = u;
        }
        __syncthreads();
#pragma unroll
        for (int ks = 0; ks < 2; ks++) {
            int k0 = kb + ks * 8;
            uint32_t a0 = Hs[r0 + g][k0 + t];
            uint32_t a1 = Hs[r0 + g + 8][k0 + t];
            uint32_t a2 = Hs[r0 + g][k0 + t + 4];
            uint32_t a3 = Hs[r0 + g + 8][k0 + t + 4];
#pragma unroll
            for (int j = 0; j < 4; j++) {
                uint32_t b0 = Ws[j * 8 + g][ks * 8 + t];
                uint32_t b1 = Ws[j * 8 + g][ks * 8 + t + 4];
                mma_tf32(acc2[j], a0, a1, a2, a3, b0, b1);
            }
        }
        __syncthreads();
    }
#pragma unroll
    for (int j = 0; j < 4; j++) {
        int col = j * 8 + 2 * t;
        int r1 = m0 + r0 + g, r2 = r1 + 8;
        if (r1 < NTOT)
            *reinterpret_cast<float2*>(g_y + (size_t)r1 * O + col) =
                make_float2(acc2[j][0], acc2[j][1]);
        if (r2 < NTOT)
            *reinterpret_cast<float2*>(g_y + (size_t)r2 * O + col) =
                make_float2(acc2[j][2], acc2[j][3]);
    }
}

// ---------------- fin2: out = h@W2r^T + aggy + b2 (K=64, N=32) ----------------
__global__ void __launch_bounds__(256) fin2_tc(const float* __restrict__ W2r,
                                               const float* __restrict__ b2,
                                               float* __restrict__ out) {
    __shared__ uint32_t As[128][20];
    __shared__ uint32_t Ws[O][20];
    const int tid = threadIdx.x;
    const int m0 = blockIdx.x * 128;
    const int warp = tid >> 5, lane = tid & 31;
    const int g = lane >> 2, t = lane & 3;
    const int r0 = warp * 16;

    float acc[4][4];
#pragma unroll
    for (int j = 0; j < 4; j++)
#pragma unroll
        for (int c = 0; c < 4; c++) acc[j][c] = 0.f;

    for (int kb = 0; kb < H; kb += 16) {
#pragma unroll
        for (int q = 0; q < 2; q++) {
            int idx = tid + 256 * q;
            int row = idx >> 2, c4 = idx & 3;
            int rg = m0 + row; if (rg > NTOT - 1) rg = NTOT - 1;
            float4 v = *reinterpret_cast<const float4*>(g_h + (size_t)rg * H + kb + c4 * 4);
            uint4 u = make_uint4(f2tf(v.x), f2tf(v.y), f2tf(v.z), f2tf(v.w));
            *reinterpret_cast<uint4*>(&As[row][c4 * 4]) = u;
        }
        if (tid < O * 4) {
            int n = tid >> 2, c4 = tid & 3;
            float4 v = *reinterpret_cast<const float4*>(W2r + (size_t)n * H + kb + c4 * 4);
            uint4 u = make_uint4(f2tf(v.x), f2tf(v.y), f2tf(v.z), f2tf(v.w));
            *reinterpret_cast<uint4*>(&Ws[n][c4 * 4]) = u;
        }
        __syncthreads();
#pragma unroll
        for (int ks = 0; ks < 2; ks++) {
            int k0 = ks * 8;
            uint32_t a0 = As[r0 + g][k0 + t];
            uint32_t a1 = As[r0 + g + 8][k0 + t];
            uint32_t a2 = As[r0 + g][k0 + t + 4];
            uint32_t a3 = As[r0 + g + 8][k0 + t + 4];
#pragma unroll
            for (int j = 0; j < 4; j++) {
                uint32_t b0 = Ws[j * 8 + g][k0 + t];
                uint32_t b1 = Ws[j * 8 + g][k0 + t + 4];
                mma_tf32(acc[j], a0, a1, a2, a3, b0, b1);
            }
        }
        __syncthreads();
    }
#pragma unroll
    for (int j = 0; j < 4; j++) {
        int col = j * 8 + 2 * t;
        float b0 = b2[col], b1v = b2[col + 1];
        int r1 = m0 + r0 + g, r2 = r1 + 8;
        if (r1 < NTOT) {
            float2 ay = *reinterpret_cast<const float2*>(g_aggy + (size_t)r1 * O + col);
            *reinterpret_cast<float2*>(out + (size_t)r1 * O + col) =
                make_float2(acc[j][0] + b0 + ay.x, acc[j][1] + b1v + ay.y);
        }
        if (r2 < NTOT) {
            float2 ay = *reinterpret_cast<const float2*>(g_aggy + (size_t)r2 * O + col);
            *reinterpret_cast<float2*>(out + (size_t)r2 * O + col) =
                make_float2(acc[j][2] + b0 + ay.x, acc[j][3] + b1v + ay.y);
        }
    }
}

// ---------------- launch -------------------------------------------------------
extern "C" void kernel_launch(void* const* d_in, const int* in_sizes, int n_in,
                              void* d_out, int out_size) {
    const float* x_product = (const float*)d_in[0];
    const int* pb_src = (const int*)d_in[1];
    const int* pb_dst = (const int*)d_in[2];
    const int* pc_src = (const int*)d_in[3];
    const int* pc_dst = (const int*)d_in[4];
    const int* ps_src = (const int*)d_in[5];
    const int* ps_dst = (const int*)d_in[6];
    const float* W_proj = (const float*)d_in[7];
    const float* b_proj = (const float*)d_in[8];
    const float* emb_brand = (const float*)d_in[9];
    const float* emb_cat = (const float*)d_in[10];
    const float* emb_shop = (const float*)d_in[11];
    const float* W1_l = (const float*)d_in[12];
    const float* b1_l = (const float*)d_in[13];
    const float* W1_r = (const float*)d_in[14];
    const float* W2_l = (const float*)d_in[15];
    const float* b2_l = (const float*)d_in[16];
    const float* W2_r = (const float*)d_in[17];
    float* out = (float*)d_out;

    const int nodeBlocks = (NTOT + 255) / 256;
    const int edgeBlocks = (3 * NE + 255) / 256;
    const int aggBlocks = (NTOT * 32 + 255) / 256;
    const int gemmBlocks = (NTOT + 127) / 128;
    const int FIN1_SMEM = (128 * 20 + 64 * 20 + 128 * 68) * 4;  // 50176

    cudaFuncSetAttribute(fin1_tc, cudaFuncAttributeMaxDynamicSharedMemorySize, FIN1_SMEM);

    static cudaStream_t s2 = nullptr;
    static cudaEvent_t evFork = nullptr, evJoin = nullptr;
    if (!s2) {
        cudaStreamCreateWithFlags(&s2, cudaStreamNonBlocking);
        cudaEventCreateWithFlags(&evFork, cudaEventDisableTiming);
        cudaEventCreateWithFlags(&evJoin, cudaEventDisableTiming);
    }

    // fork: CSR build on s2, feature assembly on main (round-5 proven DAG)
    cudaEventRecord(evFork, 0);
    cudaStreamWaitEvent(s2, evFork, 0);

    zero_deg<<<nodeBlocks, 256, 0, s2>>>();
    hist_edges<<<edgeBlocks, 256, 0, s2>>>(pb_src, pb_dst, pc_src, pc_dst, ps_src, ps_dst);
    scanA<<<NBLK_SCAN, 256, 0, s2>>>();
    scanB<<<1, 512, 0, s2>>>();
    scanC<<<nodeBlocks, 256, 0, s2>>>();
    fill_csr<<<edgeBlocks, 256, 0, s2>>>(pb_src, pb_dst, pc_src, pc_dst, ps_src, ps_dst);
    cudaEventRecord(evJoin, s2);

    proj_tc<<<(NP + 127) / 128, 256>>>(x_product, W_proj, b_proj);
    copy_emb<<<((NB + NC + NS) * H / 4 + 255) / 256, 256>>>(emb_brand, emb_cat, emb_shop);

    cudaStreamWaitEvent(0, evJoin, 0);

    // --- layer 1 ---
    aggregate64<<<aggBlocks, 256>>>();
    fin1_tc<<<gemmBlocks, 256, FIN1_SMEM>>>(W1_r, W1_l, b1_l, W2_l);
    // --- layer 2 ---
    aggregate32<<<aggBlocks, 256>>>();
    fin2_tc<<<gemmBlocks, 256>>>(W2_r, b2_l, out);
}

// round 11
// speedup vs baseline: 1.1716x; 1.0139x over previous
#include <cuda_runtime.h>
#include <cstdint>

#define NP 500000
#define NB 20000
#define NC 5000
#define NS 2000
#define NTOT 527000
#define NE 500000
#define EDIR (3 * NE * 2)
#define H 64
#define O 32
#define FIN 384

#define SCAN_SPAN 2048
#define NBLK_SCAN ((NTOT + SCAN_SPAN - 1) / SCAN_SPAN)

// ---------------- scratch ----------------------------------------------------
__device__ float g_x[(size_t)NTOT * H];
__device__ float g_h[(size_t)NTOT * H];
__device__ float g_agg[(size_t)NTOT * H];    // layer-1 mean of x (64-dim)
__device__ float g_y[(size_t)NTOT * O];      // y = relu(h) @ W2_l^T (32-dim)
__device__ float g_aggy[(size_t)NTOT * O];   // layer-2 mean of y (32-dim)
__device__ int   g_deg[NTOT];
__device__ int   g_rowstart[NTOT];
__device__ int   g_cursor[NTOT];
__device__ int   g_scaninc[NTOT];
__device__ int   g_blocksum[512];
__device__ int   g_adj[EDIR];

// ---------------- tf32 helpers ----------------------------------------------
__device__ __forceinline__ uint32_t f2tf(float x) {
    uint32_t r;
    asm("cvt.rna.tf32.f32 %0, %1;" : "=r"(r) : "f"(x));
    return r;
}
__device__ __forceinline__ void mma_tf32(float* d, uint32_t a0, uint32_t a1,
                                         uint32_t a2, uint32_t a3,
                                         uint32_t b0, uint32_t b1) {
    asm volatile(
        "mma.sync.aligned.m16n8k8.row.col.f32.tf32.tf32.f32 "
        "{%0,%1,%2,%3},{%4,%5,%6,%7},{%8,%9},{%0,%1,%2,%3};"
        : "+f"(d[0]), "+f"(d[1]), "+f"(d[2]), "+f"(d[3])
        : "r"(a0), "r"(a1), "r"(a2), "r"(a3), "r"(b0), "r"(b1));
}

// ---------------- CSR build ---------------------------------------------------
__global__ void __launch_bounds__(256) zero_deg() {
    int i = blockIdx.x * 256 + threadIdx.x;
    if (i < NTOT) g_deg[i] = 0;
}

__global__ void __launch_bounds__(256) hist_edges(
    const int* __restrict__ pb_src, const int* __restrict__ pb_dst,
    const int* __restrict__ pc_src, const int* __restrict__ pc_dst,
    const int* __restrict__ ps_src, const int* __restrict__ ps_dst) {
    int e = blockIdx.x * 256 + threadIdx.x;
    if (e >= 3 * NE) return;
    int t = e / NE, i = e - t * NE;
    const int* sp; const int* dp; int off;
    if (t == 0)      { sp = pb_src; dp = pb_dst; off = NP; }
    else if (t == 1) { sp = pc_src; dp = pc_dst; off = NP + NB; }
    else             { sp = ps_src; dp = ps_dst; off = NP + NB + NC; }
    int p = __ldg(sp + i);
    int o = __ldg(dp + i) + off;
    atomicAdd(&g_deg[p], 1);
    atomicAdd(&g_deg[o], 1);
}

__global__ void __launch_bounds__(256) scanA() {
    __shared__ int wsum[8];
    __shared__ int wpre[8];
    int tid = threadIdx.x, lane = tid & 31, wid = tid >> 5;
    int base = blockIdx.x * SCAN_SPAN + tid * 8;
    int v[8], run = 0;
#pragma unroll
    for (int t = 0; t < 8; t++) {
        int idx = base + t;
        int d = (idx < NTOT) ? g_deg[idx] : 0;
        run += d;
        v[t] = run;
    }
    int tot = run;
#pragma unroll
    for (int off = 1; off < 32; off <<= 1) {
        int n = __shfl_up_sync(0xffffffffu, tot, off);
        if (lane >= off) tot += n;
    }
    int wexcl = tot - run;
    if (lane == 31) wsum[wid] = tot;
    __syncthreads();
    if (tid < 8) {
        int s = wsum[tid];
        int r = s;
#pragma unroll
        for (int off = 1; off < 8; off <<= 1) {
            int n = __shfl_up_sync(0xffu, r, off);
            if (tid >= off) r += n;
        }
        wpre[tid] = r - s;
        if (tid == 7) g_blocksum[blockIdx.x] = r;
    }
    __syncthreads();
    int bexcl = wexcl + wpre[wid];
#pragma unroll
    for (int t = 0; t < 8; t++) {
        int idx = base + t;
        if (idx < NTOT) g_scaninc[idx] = v[t] + bexcl;
    }
}

__global__ void __launch_bounds__(512) scanB() {
    __shared__ int s[NBLK_SCAN];
    int tid = threadIdx.x;
    if (tid < NBLK_SCAN) s[tid] = g_blocksum[tid];
    __syncthreads();
    if (tid == 0) {
        int run = 0;
        for (int i = 0; i < NBLK_SCAN; i++) { int t = s[i]; s[i] = run; run += t; }
    }
    __syncthreads();
    if (tid < NBLK_SCAN) g_blocksum[tid] = s[tid];
}

__global__ void __launch_bounds__(256) scanC() {
    int i = blockIdx.x * 256 + threadIdx.x;
    if (i >= NTOT) return;
    int start = g_scaninc[i] + g_blocksum[i >> 11] - g_deg[i];
    g_rowstart[i] = start;
    g_cursor[i] = start;
}

__global__ void __launch_bounds__(256) fill_csr(
    const int* __restrict__ pb_src, const int* __restrict__ pb_dst,
    const int* __restrict__ pc_src, const int* __restrict__ pc_dst,
    const int* __restrict__ ps_src, const int* __restrict__ ps_dst) {
    int e = blockIdx.x * 256 + threadIdx.x;
    if (e >= 3 * NE) return;
    int t = e / NE, i = e - t * NE;
    const int* sp; const int* dp; int off;
    if (t == 0)      { sp = pb_src; dp = pb_dst; off = NP; }
    else if (t == 1) { sp = pc_src; dp = pc_dst; off = NP + NB; }
    else             { sp = ps_src; dp = ps_dst; off = NP + NB + NC; }
    int p = __ldg(sp + i);
    int o = __ldg(dp + i) + off;
    int pos = atomicAdd(&g_cursor[o], 1);
    g_adj[pos] = p;
    int pos2 = atomicAdd(&g_cursor[p], 1);
    g_adj[pos2] = o;
}

// ---------------- feature assembly --------------------------------------------
__global__ void __launch_bounds__(256) copy_emb(const float* __restrict__ eb,
                                                const float* __restrict__ ec,
                                                const float* __restrict__ es) {
    int i = blockIdx.x * 256 + threadIdx.x;
    const int tot = (NB + NC + NS) * H / 4;
    if (i >= tot) return;
    const int nb4 = NB * H / 4, nc4 = NC * H / 4;
    float4 v;
    if (i < nb4) v = reinterpret_cast<const float4*>(eb)[i];
    else if (i < nb4 + nc4) v = reinterpret_cast<const float4*>(ec)[i - nb4];
    else v = reinterpret_cast<const float4*>(es)[i - nb4 - nc4];
    reinterpret_cast<float4*>(g_x)[(size_t)NP * H / 4 + i] = v;
}

// ---------------- proj: relu(x_product @ W_proj^T + b) via tf32 HMMA ----------
__global__ void __launch_bounds__(256) proj_tc(const float* __restrict__ A,
                                               const float* __restrict__ W,
                                               const float* __restrict__ bias) {
    __shared__ uint32_t As[128][20];
    __shared__ uint32_t Ws[64][20];
    const int tid = threadIdx.x;
    const int m0 = blockIdx.x * 128;
    const int warp = tid >> 5, lane = tid & 31;
    const int g = lane >> 2, t = lane & 3;

    float acc[8][4];
#pragma unroll
    for (int j = 0; j < 8; j++)
#pragma unroll
        for (int c = 0; c < 4; c++) acc[j][c] = 0.f;

    for (int kb = 0; kb < FIN; kb += 16) {
#pragma unroll
        for (int q = 0; q < 2; q++) {
            int idx = tid + 256 * q;
            int row = idx >> 2, c4 = idx & 3;
            int rg = m0 + row; if (rg > NP - 1) rg = NP - 1;
            float4 v = *reinterpret_cast<const float4*>(A + (size_t)rg * FIN + kb + c4 * 4);
            uint4 u = make_uint4(f2tf(v.x), f2tf(v.y), f2tf(v.z), f2tf(v.w));
            *reinterpret_cast<uint4*>(&As[row][c4 * 4]) = u;
        }
        {
            int n = tid >> 2, c4 = tid & 3;
            float4 v = *reinterpret_cast<const float4*>(W + (size_t)n * FIN + kb + c4 * 4);
            uint4 u = make_uint4(f2tf(v.x), f2tf(v.y), f2tf(v.z), f2tf(v.w));
            *reinterpret_cast<uint4*>(&Ws[n][c4 * 4]) = u;
        }
        __syncthreads();
        const int r0 = warp * 16;
#pragma unroll
        for (int ks = 0; ks < 2; ks++) {
            int k0 = ks * 8;
            uint32_t a0 = As[r0 + g][k0 + t];
            uint32_t a1 = As[r0 + g + 8][k0 + t];
            uint32_t a2 = As[r0 + g][k0 + t + 4];
            uint32_t a3 = As[r0 + g + 8][k0 + t + 4];
#pragma unroll
            for (int j = 0; j < 8; j++) {
                uint32_t b0 = Ws[j * 8 + g][k0 + t];
                uint32_t b1 = Ws[j * 8 + g][k0 + t + 4];
                mma_tf32(acc[j], a0, a1, a2, a3, b0, b1);
            }
        }
        __syncthreads();
    }
#pragma unroll
    for (int j = 0; j < 8; j++) {
        int col = j * 8 + 2 * t;
        float b0 = bias[col], b1 = bias[col + 1];
        int r1 = m0 + warp * 16 + g;
        if (r1 < NP) {
            float2 o = make_float2(fmaxf(acc[j][0] + b0, 0.f), fmaxf(acc[j][1] + b1, 0.f));
            *reinterpret_cast<float2*>(g_x + (size_t)r1 * H + col) = o;
        }
        int r2 = r1 + 8;
        if (r2 < NP) {
            float2 o = make_float2(fmaxf(acc[j][2] + b0, 0.f), fmaxf(acc[j][3] + b1, 0.f));
            *reinterpret_cast<float2*>(g_x + (size_t)r2 * H + col) = o;
        }
    }
}

// ---------------- layer-1 aggregation: mean of x (64-dim), round-5 body -------
__global__ void __launch_bounds__(256) aggregate64() {
    int gw = (blockIdx.x * 256 + threadIdx.x) >> 5;
    if (gw >= NTOT) return;
    int node = NTOT - 1 - gw;     // heavy (high-id) rows first
    int lane = threadIdx.x & 31;
    int start = g_rowstart[node];
    int deg = g_deg[node];
    int half = lane >> 4;
    int f = (lane & 15) * 4;
    float4 acc0 = make_float4(0.f, 0.f, 0.f, 0.f);
    float4 acc1 = make_float4(0.f, 0.f, 0.f, 0.f);
    int i = half;
    for (; i + 2 < deg; i += 4) {
        int s0 = __ldg(g_adj + start + i);
        int s1 = __ldg(g_adj + start + i + 2);
        float4 v0 = *reinterpret_cast<const float4*>(g_x + (size_t)s0 * H + f);
        float4 v1 = *reinterpret_cast<const float4*>(g_x + (size_t)s1 * H + f);
        acc0.x += v0.x; acc0.y += v0.y; acc0.z += v0.z; acc0.w += v0.w;
        acc1.x += v1.x; acc1.y += v1.y; acc1.z += v1.z; acc1.w += v1.w;
    }
    if (i < deg) {
        int s0 = __ldg(g_adj + start + i);
        float4 v0 = *reinterpret_cast<const float4*>(g_x + (size_t)s0 * H + f);
        acc0.x += v0.x; acc0.y += v0.y; acc0.z += v0.z; acc0.w += v0.w;
    }
    acc0.x += acc1.x; acc0.y += acc1.y; acc0.z += acc1.z; acc0.w += acc1.w;
    acc0.x += __shfl_xor_sync(0xffffffffu, acc0.x, 16);
    acc0.y += __shfl_xor_sync(0xffffffffu, acc0.y, 16);
    acc0.z += __shfl_xor_sync(0xffffffffu, acc0.z, 16);
    acc0.w += __shfl_xor_sync(0xffffffffu, acc0.w, 16);
    if (lane < 16) {
        float inv = 1.f / fmaxf((float)deg, 1.f);
        float4 o = make_float4(acc0.x * inv, acc0.y * inv, acc0.z * inv, acc0.w * inv);
        *reinterpret_cast<float4*>(g_agg + (size_t)node * H + f) = o;
    }
}

// ---------------- layer-2 aggregation: mean of y (32-dim), quarter-warps ------
__global__ void __launch_bounds__(256) aggregate32() {
    int gw = (blockIdx.x * 256 + threadIdx.x) >> 5;
    if (gw >= NTOT) return;
    int node = NTOT - 1 - gw;
    int lane = threadIdx.x & 31;
    int start = g_rowstart[node];
    int deg = g_deg[node];
    int q = lane >> 3;            // quarter 0..3
    int f = (lane & 7) * 4;       // feature offset within 32
    float4 acc0 = make_float4(0.f, 0.f, 0.f, 0.f);
    float4 acc1 = make_float4(0.f, 0.f, 0.f, 0.f);
    int i = q;
    for (; i + 4 < deg; i += 8) {
        int s0 = __ldg(g_adj + start + i);
        int s1 = __ldg(g_adj + start + i + 4);
        float4 v0 = *reinterpret_cast<const float4*>(g_y + (size_t)s0 * O + f);
        float4 v1 = *reinterpret_cast<const float4*>(g_y + (size_t)s1 * O + f);
        acc0.x += v0.x; acc0.y += v0.y; acc0.z += v0.z; acc0.w += v0.w;
        acc1.x += v1.x; acc1.y += v1.y; acc1.z += v1.z; acc1.w += v1.w;
    }
    if (i < deg) {
        int s0 = __ldg(g_adj + start + i);
        float4 v0 = *reinterpret_cast<const float4*>(g_y + (size_t)s0 * O + f);
        acc0.x += v0.x; acc0.y += v0.y; acc0.z += v0.z; acc0.w += v0.w;
    }
    acc0.x += acc1.x; acc0.y += acc1.y; acc0.z += acc1.z; acc0.w += acc1.w;
    acc0.x += __shfl_xor_sync(0xffffffffu, acc0.x, 8);
    acc0.y += __shfl_xor_sync(0xffffffffu, acc0.y, 8);
    acc0.z += __shfl_xor_sync(0xffffffffu, acc0.z, 8);
    acc0.w += __shfl_xor_sync(0xffffffffu, acc0.w, 8);
    acc0.x += __shfl_xor_sync(0xffffffffu, acc0.x, 16);
    acc0.y += __shfl_xor_sync(0xffffffffu, acc0.y, 16);
    acc0.z += __shfl_xor_sync(0xffffffffu, acc0.z, 16);
    acc0.w += __shfl_xor_sync(0xffffffffu, acc0.w, 16);
    if (lane < 8) {
        float inv = 1.f / fmaxf((float)deg, 1.f);
        float4 o = make_float4(acc0.x * inv, acc0.y * inv, acc0.z * inv, acc0.w * inv);
        *reinterpret_cast<float4*>(g_aggy + (size_t)node * O + f) = o;
    }
}

// ---------------- SAGE finalize layer 1 (exact round-5 body) ------------------
// h = relu(x@W1r^T + agg@W1l^T + b1) -> g_h
__global__ void __launch_bounds__(256) finalize1_tc(const float* __restrict__ Wr,
                                                    const float* __restrict__ Wl,
                                                    const float* __restrict__ bias) {
    __shared__ uint32_t As[128][20];
    __shared__ uint32_t Ws[64][20];
    const int tid = threadIdx.x;
    const int m0 = blockIdx.x * 128;
    const int warp = tid >> 5, lane = tid & 31;
    const int g = lane >> 2, t = lane & 3;

    float acc[8][4];
#pragma unroll
    for (int j = 0; j < 8; j++)
#pragma unroll
        for (int c = 0; c < 4; c++) acc[j][c] = 0.f;

    for (int kb = 0; kb < 2 * H; kb += 16) {
        const float* src = (kb < H) ? g_x : g_agg;
        const float* W = (kb < H) ? Wr : Wl;
        const int kcol = kb & (H - 1);
#pragma unroll
        for (int q = 0; q < 2; q++) {
            int idx = tid + 256 * q;
            int row = idx >> 2, c4 = idx & 3;
            int rg = m0 + row; if (rg > NTOT - 1) rg = NTOT - 1;
            float4 v = *reinterpret_cast<const float4*>(src + (size_t)rg * H + kcol + c4 * 4);
            uint4 u = make_uint4(f2tf(v.x), f2tf(v.y), f2tf(v.z), f2tf(v.w));
            *reinterpret_cast<uint4*>(&As[row][c4 * 4]) = u;
        }
        {
            int n = tid >> 2, c4 = tid & 3;
            float4 v = *reinterpret_cast<const float4*>(W + (size_t)n * H + kcol + c4 * 4);
            uint4 u = make_uint4(f2tf(v.x), f2tf(v.y), f2tf(v.z), f2tf(v.w));
            *reinterpret_cast<uint4*>(&Ws[n][c4 * 4]) = u;
        }
        __syncthreads();
        const int r0 = warp * 16;
#pragma unroll
        for (int ks = 0; ks < 2; ks++) {
            int k0 = ks * 8;
            uint32_t a0 = As[r0 + g][k0 + t];
            uint32_t a1 = As[r0 + g + 8][k0 + t];
            uint32_t a2 = As[r0 + g][k0 + t + 4];
            uint32_t a3 = As[r0 + g + 8][k0 + t + 4];
#pragma unroll
            for (int j = 0; j < 8; j++) {
                uint32_t b0 = Ws[j * 8 + g][k0 + t];
                uint32_t b1 = Ws[j * 8 + g][k0 + t + 4];
                mma_tf32(acc[j], a0, a1, a2, a3, b0, b1);
            }
        }
        __syncthreads();
    }
#pragma unroll
    for (int j = 0; j < 8; j++) {
        int col = j * 8 + 2 * t;
        float b0 = bias[col], b1 = bias[col + 1];
        int r1 = m0 + warp * 16 + g;
        if (r1 < NTOT) {
            float2 o = make_float2(fmaxf(acc[j][0] + b0, 0.f), fmaxf(acc[j][1] + b1, 0.f));
            *reinterpret_cast<float2*>(g_h + (size_t)r1 * H + col) = o;
        }
        int r2 = r1 + 8;
        if (r2 < NTOT) {
            float2 o = make_float2(fmaxf(acc[j][2] + b0, 0.f), fmaxf(acc[j][3] + b1, 0.f));
            *reinterpret_cast<float2*>(g_h + (size_t)r2 * H + col) = o;
        }
    }
}

// ---------------- y = h @ W2l^T (streaming GEMM, K=64, N=32) ------------------
__global__ void __launch_bounds__(256) y_tc(const float* __restrict__ W2l) {
    __shared__ uint32_t As[128][20];
    __shared__ uint32_t Ws[O][20];
    const int tid = threadIdx.x;
    const int m0 = blockIdx.x * 128;
    const int warp = tid >> 5, lane = tid & 31;
    const int g = lane >> 2, t = lane & 3;
    const int r0 = warp * 16;

    float acc[4][4];
#pragma unroll
    for (int j = 0; j < 4; j++)
#pragma unroll
        for (int c = 0; c < 4; c++) acc[j][c] = 0.f;

    for (int kb = 0; kb < H; kb += 16) {
#pragma unroll
        for (int q = 0; q < 2; q++) {
            int idx = tid + 256 * q;
            int row = idx >> 2, c4 = idx & 3;
            int rg = m0 + row; if (rg > NTOT - 1) rg = NTOT - 1;
            float4 v = *reinterpret_cast<const float4*>(g_h + (size_t)rg * H + kb + c4 * 4);
            uint4 u = make_uint4(f2tf(v.x), f2tf(v.y), f2tf(v.z), f2tf(v.w));
            *reinterpret_cast<uint4*>(&As[row][c4 * 4]) = u;
        }
        if (tid < O * 4) {
            int n = tid >> 2, c4 = tid & 3;
            float4 v = *reinterpret_cast<const float4*>(W2l + (size_t)n * H + kb + c4 * 4);
            uint4 u = make_uint4(f2tf(v.x), f2tf(v.y), f2tf(v.z), f2tf(v.w));
            *reinterpret_cast<uint4*>(&Ws[n][c4 * 4]) = u;
        }
        __syncthreads();
#pragma unroll
        for (int ks = 0; ks < 2; ks++) {
            int k0 = ks * 8;
            uint32_t a0 = As[r0 + g][k0 + t];
            uint32_t a1 = As[r0 + g + 8][k0 + t];
            uint32_t a2 = As[r0 + g][k0 + t + 4];
            uint32_t a3 = As[r0 + g + 8][k0 + t + 4];
#pragma unroll
            for (int j = 0; j < 4; j++) {
                uint32_t b0 = Ws[j * 8 + g][k0 + t];
                uint32_t b1 = Ws[j * 8 + g][k0 + t + 4];
                mma_tf32(acc[j], a0, a1, a2, a3, b0, b1);
            }
        }
        __syncthreads();
    }
#pragma unroll
    for (int j = 0; j < 4; j++) {
        int col = j * 8 + 2 * t;
        int r1 = m0 + r0 + g, r2 = r1 + 8;
        if (r1 < NTOT)
            *reinterpret_cast<float2*>(g_y + (size_t)r1 * O + col) =
                make_float2(acc[j][0], acc[j][1]);
        if (r2 < NTOT)
            *reinterpret_cast<float2*>(g_y + (size_t)r2 * O + col) =
                make_float2(acc[j][2], acc[j][3]);
    }
}

// ---------------- fin2: out = h@W2r^T + aggy + b2 (K=64, N=32) ----------------
__global__ void __launch_bounds__(256) fin2_tc(const float* __restrict__ W2r,
                                               const float* __restrict__ b2,
                                               float* __restrict__ out) {
    __shared__ uint32_t As[128][20];
    __shared__ uint32_t Ws[O][20];
    const int tid = threadIdx.x;
    const int m0 = blockIdx.x * 128;
    const int warp = tid >> 5, lane = tid & 31;
    const int g = lane >> 2, t = lane & 3;
    const int r0 = warp * 16;

    float acc[4][4];
#pragma unroll
    for (int j = 0; j < 4; j++)
#pragma unroll
        for (int c = 0; c < 4; c++) acc[j][c] = 0.f;

    for (int kb = 0; kb < H; kb += 16) {
#pragma unroll
        for (int q = 0; q < 2; q++) {
            int idx = tid + 256 * q;
            int row = idx >> 2, c4 = idx & 3;
            int rg = m0 + row; if (rg > NTOT - 1) rg = NTOT - 1;
            float4 v = *reinterpret_cast<const float4*>(g_h + (size_t)rg * H + kb + c4 * 4);
            uint4 u = make_uint4(f2tf(v.x), f2tf(v.y), f2tf(v.z), f2tf(v.w));
            *reinterpret_cast<uint4*>(&As[row][c4 * 4]) = u;
        }
        if (tid < O * 4) {
            int n = tid >> 2, c4 = tid & 3;
            float4 v = *reinterpret_cast<const float4*>(W2r + (size_t)n * H + kb + c4 * 4);
            uint4 u = make_uint4(f2tf(v.x), f2tf(v.y), f2tf(v.z), f2tf(v.w));
            *reinterpret_cast<uint4*>(&Ws[n][c4 * 4]) = u;
        }
        __syncthreads();
#pragma unroll
        for (int ks = 0; ks < 2; ks++) {
            int k0 = ks * 8;
            uint32_t a0 = As[r0 + g][k0 + t];
            uint32_t a1 = As[r0 + g + 8][k0 + t];
            uint32_t a2 = As[r0 + g][k0 + t + 4];
            uint32_t a3 = As[r0 + g + 8][k0 + t + 4];
#pragma unroll
            for (int j = 0; j < 4; j++) {
                uint32_t b0 = Ws[j * 8 + g][k0 + t];
                uint32_t b1 = Ws[j * 8 + g][k0 + t + 4];
                mma_tf32(acc[j], a0, a1, a2, a3, b0, b1);
            }
        }
        __syncthreads();
    }
#pragma unroll
    for (int j = 0; j < 4; j++) {
        int col = j * 8 + 2 * t;
        float b0 = b2[col], b1v = b2[col + 1];
        int r1 = m0 + r0 + g, r2 = r1 + 8;
        if (r1 < NTOT) {
            float2 ay = *reinterpret_cast<const float2*>(g_aggy + (size_t)r1 * O + col);
            *reinterpret_cast<float2*>(out + (size_t)r1 * O + col) =
                make_float2(acc[j][0] + b0 + ay.x, acc[j][1] + b1v + ay.y);
        }
        if (r2 < NTOT) {
            float2 ay = *reinterpret_cast<const float2*>(g_aggy + (size_t)r2 * O + col);
            *reinterpret_cast<float2*>(out + (size_t)r2 * O + col) =
                make_float2(acc[j][2] + b0 + ay.x, acc[j][3] + b1v + ay.y);
        }
    }
}

// ---------------- launch -------------------------------------------------------
extern "C" void kernel_launch(void* const* d_in, const int* in_sizes, int n_in,
                              void* d_out, int out_size) {
    const float* x_product = (const float*)d_in[0];
    const int* pb_src = (const int*)d_in[1];
    const int* pb_dst = (const int*)d_in[2];
    const int* pc_src = (const int*)d_in[3];
    const int* pc_dst = (const int*)d_in[4];
    const int* ps_src = (const int*)d_in[5];
    const int* ps_dst = (const int*)d_in[6];
    const float* W_proj = (const float*)d_in[7];
    const float* b_proj = (const float*)d_in[8];
    const float* emb_brand = (const float*)d_in[9];
    const float* emb_cat = (const float*)d_in[10];
    const float* emb_shop = (const float*)d_in[11];
    const float* W1_l = (const float*)d_in[12];
    const float* b1_l = (const float*)d_in[13];
    const float* W1_r = (const float*)d_in[14];
    const float* W2_l = (const float*)d_in[15];
    const float* b2_l = (const float*)d_in[16];
    const float* W2_r = (const float*)d_in[17];
    float* out = (float*)d_out;

    const int nodeBlocks = (NTOT + 255) / 256;
    const int edgeBlocks = (3 * NE + 255) / 256;
    const int aggBlocks = (NTOT * 32 + 255) / 256;
    const int gemmBlocks = (NTOT + 127) / 128;

    static cudaStream_t s2 = nullptr;
    static cudaEvent_t evFork = nullptr, evJoin = nullptr;
    if (!s2) {
        cudaStreamCreateWithFlags(&s2, cudaStreamNonBlocking);
        cudaEventCreateWithFlags(&evFork, cudaEventDisableTiming);
        cudaEventCreateWithFlags(&evJoin, cudaEventDisableTiming);
    }

    // fork: CSR build on s2, feature assembly on main (round-5 proven DAG)
    cudaEventRecord(evFork, 0);
    cudaStreamWaitEvent(s2, evFork, 0);

    zero_deg<<<nodeBlocks, 256, 0, s2>>>();
    hist_edges<<<edgeBlocks, 256, 0, s2>>>(pb_src, pb_dst, pc_src, pc_dst, ps_src, ps_dst);
    scanA<<<NBLK_SCAN, 256, 0, s2>>>();
    scanB<<<1, 512, 0, s2>>>();
    scanC<<<nodeBlocks, 256, 0, s2>>>();
    fill_csr<<<edgeBlocks, 256, 0, s2>>>(pb_src, pb_dst, pc_src, pc_dst, ps_src, ps_dst);
    cudaEventRecord(evJoin, s2);

    proj_tc<<<(NP + 127) / 128, 256>>>(x_product, W_proj, b_proj);
    copy_emb<<<((NB + NC + NS) * H / 4 + 255) / 256, 256>>>(emb_brand, emb_cat, emb_shop);

    cudaStreamWaitEvent(0, evJoin, 0);

    // --- layer 1 ---
    aggregate64<<<aggBlocks, 256>>>();
    finalize1_tc<<<gemmBlocks, 256>>>(W1_r, W1_l, b1_l);
    // --- y projection + layer 2 ---
    y_tc<<<gemmBlocks, 256>>>(W2_l);
    aggregate32<<<aggBlocks, 256>>>();
    fin2_tc<<<gemmBlocks, 256>>>(W2_r, b2_l, out);
}